// round 3
// baseline (speedup 1.0000x reference)
#include <cuda_runtime.h>
#include <cuda_bf16.h>
#include <math.h>
#include <stdint.h>

// Problem dims
#define TT   512
#define BB   128
#define II   512
#define HH   512
#define G4   2048
#define NBLK 64          // persistent blocks for recurrence (32 gate-cols each)
#define TBH  ((size_t)TT * BB * HH)

// ---------------------------------------------------------------------------
// Device scratch (allocation-free rule)
// ---------------------------------------------------------------------------
__device__ __nv_bfloat16 g_Xhi[(size_t)TT * BB * II];   // 64MB
__device__ __nv_bfloat16 g_Xlo[(size_t)TT * BB * II];   // 64MB
__device__ __nv_bfloat16 g_Whi[G4 * II];                // 2MB
__device__ __nv_bfloat16 g_Wlo[G4 * II];                // 2MB
__device__ float         g_bias[G4];
__device__ float         g_xg[(size_t)TT * BB * G4];    // 512MB
__device__ uint32_t      g_hpk[2][BB * HH];             // packed {hi,lo} bf16 of h, double-buffered
__device__ unsigned      g_sync;

// ---------------------------------------------------------------------------
// Helpers
// ---------------------------------------------------------------------------
__device__ __forceinline__ void split2(float x, uint32_t& h, uint32_t& l) {
    __nv_bfloat16 hb = __float2bfloat16_rn(x);
    float r = x - __bfloat162float(hb);
    __nv_bfloat16 lb = __float2bfloat16_rn(r);
    h = (uint32_t)__bfloat16_as_ushort(hb);
    l = (uint32_t)__bfloat16_as_ushort(lb);
}

__device__ __forceinline__ uint32_t smem_u32(const void* p) {
    return (uint32_t)__cvta_generic_to_shared(p);
}

__device__ __forceinline__ void ldmx4(uint32_t& r0, uint32_t& r1, uint32_t& r2, uint32_t& r3,
                                      uint32_t addr) {
    asm volatile("ldmatrix.sync.aligned.m8n8.x4.shared.b16 {%0,%1,%2,%3}, [%4];"
                 : "=r"(r0), "=r"(r1), "=r"(r2), "=r"(r3) : "r"(addr));
}
__device__ __forceinline__ void ldmx2(uint32_t& r0, uint32_t& r1, uint32_t addr) {
    asm volatile("ldmatrix.sync.aligned.m8n8.x2.shared.b16 {%0,%1}, [%2];"
                 : "=r"(r0), "=r"(r1) : "r"(addr));
}
__device__ __forceinline__ void mma_bf16(float* d, const uint32_t* a, const uint32_t* b) {
    asm volatile(
        "mma.sync.aligned.m16n8k16.row.col.f32.bf16.bf16.f32 "
        "{%0,%1,%2,%3}, {%4,%5,%6,%7}, {%8,%9}, {%0,%1,%2,%3};"
        : "+f"(d[0]), "+f"(d[1]), "+f"(d[2]), "+f"(d[3])
        : "r"(a[0]), "r"(a[1]), "r"(a[2]), "r"(a[3]), "r"(b[0]), "r"(b[1]));
}

// ---------------------------------------------------------------------------
// convert_init: split X and W_ih into bf16 hi/lo, build bias, zero sync.
// ---------------------------------------------------------------------------
__global__ void convert_init(const float* __restrict__ X, const float* __restrict__ W,
                             const float* __restrict__ b1, const float* __restrict__ b2)
{
    size_t i0 = (size_t)blockIdx.x * blockDim.x + threadIdx.x;
    size_t stride = (size_t)gridDim.x * blockDim.x;
    const size_t NX4 = (size_t)TT * BB * II / 4;
    const size_t NW4 = (size_t)G4 * II / 4;

    for (size_t i = i0; i < NX4; i += stride) {
        float4 v = ((const float4*)X)[i];
        uint32_t h0, h1, h2, h3, l0, l1, l2, l3;
        split2(v.x, h0, l0); split2(v.y, h1, l1);
        split2(v.z, h2, l2); split2(v.w, h3, l3);
        ((uint2*)g_Xhi)[i] = make_uint2(h0 | (h1 << 16), h2 | (h3 << 16));
        ((uint2*)g_Xlo)[i] = make_uint2(l0 | (l1 << 16), l2 | (l3 << 16));
    }
    for (size_t i = i0; i < NW4; i += stride) {
        float4 v = ((const float4*)W)[i];
        uint32_t h0, h1, h2, h3, l0, l1, l2, l3;
        split2(v.x, h0, l0); split2(v.y, h1, l1);
        split2(v.z, h2, l2); split2(v.w, h3, l3);
        ((uint2*)g_Whi)[i] = make_uint2(h0 | (h1 << 16), h2 | (h3 << 16));
        ((uint2*)g_Wlo)[i] = make_uint2(l0 | (l1 << 16), l2 | (l3 << 16));
    }
    for (size_t i = i0; i < G4; i += stride) g_bias[i] = b1[i] + b2[i];
    if (i0 == 0) g_sync = 0u;
}

// ---------------------------------------------------------------------------
// sgemm_bf16: g_xg[m][n] = sum_k X[m][k] * W_ih[n][k] + bias[n]
// (unchanged from round 2)
// ---------------------------------------------------------------------------
__global__ void __launch_bounds__(256) sgemm_bf16()
{
    __shared__ __nv_bfloat16 Ah[128 * 40], Al[128 * 40], Bh[128 * 40], Bl[128 * 40];

    const int t    = threadIdx.x;
    const int lane = t & 31;
    const int w    = t >> 5;
    const int wm   = w >> 1;
    const int wn   = w & 1;
    const int m0   = blockIdx.y * 128;
    const int n0   = blockIdx.x * 128;

    const int row0 = t >> 2;
    const int grp  = t & 3;
    size_t ao0 = (size_t)(m0 + row0) * II + grp * 8;
    size_t ao1 = ao0 + (size_t)64 * II;
    size_t bo0 = (size_t)(n0 + row0) * II + grp * 8;
    size_t bo1 = bo0 + (size_t)64 * II;
    const int s0 = row0 * 40 + grp * 8;
    const int s1 = s0 + 64 * 40;

    const uint32_t uAh = smem_u32(Ah), uAl = smem_u32(Al);
    const uint32_t uBh = smem_u32(Bh), uBl = smem_u32(Bl);
    const int a_r = lane & 15, a_c = (lane >> 4) << 3;
    const int b_r = lane & 7,  b_c = ((lane >> 3) & 1) << 3;

    float d[2][8][4] = {{{0.f}}};

    uint4 pAh0 = *(const uint4*)(g_Xhi + ao0);
    uint4 pAh1 = *(const uint4*)(g_Xhi + ao1);
    uint4 pAl0 = *(const uint4*)(g_Xlo + ao0);
    uint4 pAl1 = *(const uint4*)(g_Xlo + ao1);
    uint4 pBh0 = *(const uint4*)(g_Whi + bo0);
    uint4 pBh1 = *(const uint4*)(g_Whi + bo1);
    uint4 pBl0 = *(const uint4*)(g_Wlo + bo0);
    uint4 pBl1 = *(const uint4*)(g_Wlo + bo1);

    for (int it = 0; it < 16; ++it) {
        __syncthreads();
        *(uint4*)(Ah + s0) = pAh0; *(uint4*)(Ah + s1) = pAh1;
        *(uint4*)(Al + s0) = pAl0; *(uint4*)(Al + s1) = pAl1;
        *(uint4*)(Bh + s0) = pBh0; *(uint4*)(Bh + s1) = pBh1;
        *(uint4*)(Bl + s0) = pBl0; *(uint4*)(Bl + s1) = pBl1;
        __syncthreads();

        if (it != 15) {
            ao0 += 32; ao1 += 32; bo0 += 32; bo1 += 32;
            pAh0 = *(const uint4*)(g_Xhi + ao0);
            pAh1 = *(const uint4*)(g_Xhi + ao1);
            pAl0 = *(const uint4*)(g_Xlo + ao0);
            pAl1 = *(const uint4*)(g_Xlo + ao1);
            pBh0 = *(const uint4*)(g_Whi + bo0);
            pBh1 = *(const uint4*)(g_Whi + bo1);
            pBl0 = *(const uint4*)(g_Wlo + bo0);
            pBl1 = *(const uint4*)(g_Wlo + bo1);
        }

#pragma unroll
        for (int ks = 0; ks < 2; ++ks) {
            uint32_t ah[2][4], al[2][4];
#pragma unroll
            for (int mt = 0; mt < 2; ++mt) {
                uint32_t ra = uAh + (uint32_t)(((wm * 32 + mt * 16 + a_r) * 40 + ks * 16 + a_c) * 2);
                ldmx4(ah[mt][0], ah[mt][1], ah[mt][2], ah[mt][3], ra);
                uint32_t rl = uAl + (uint32_t)(((wm * 32 + mt * 16 + a_r) * 40 + ks * 16 + a_c) * 2);
                ldmx4(al[mt][0], al[mt][1], al[mt][2], al[mt][3], rl);
            }
#pragma unroll
            for (int nt = 0; nt < 8; ++nt) {
                uint32_t bh[2], bl[2];
                uint32_t rb = uBh + (uint32_t)(((wn * 64 + nt * 8 + b_r) * 40 + ks * 16 + b_c) * 2);
                ldmx2(bh[0], bh[1], rb);
                uint32_t rlb = uBl + (uint32_t)(((wn * 64 + nt * 8 + b_r) * 40 + ks * 16 + b_c) * 2);
                ldmx2(bl[0], bl[1], rlb);
#pragma unroll
                for (int mt = 0; mt < 2; ++mt) {
                    mma_bf16(d[mt][nt], ah[mt], bh);
                    mma_bf16(d[mt][nt], ah[mt], bl);
                    mma_bf16(d[mt][nt], al[mt], bh);
                }
            }
        }
    }

    const int gid = lane >> 2, tig = lane & 3;
#pragma unroll
    for (int mt = 0; mt < 2; ++mt) {
#pragma unroll
        for (int nt = 0; nt < 8; ++nt) {
            int col = n0 + wn * 64 + nt * 8 + 2 * tig;
            float bb0 = g_bias[col], bb1 = g_bias[col + 1];
            int r = m0 + wm * 32 + mt * 16 + gid;
            float2 v0 = make_float2(d[mt][nt][0] + bb0, d[mt][nt][1] + bb1);
            float2 v1 = make_float2(d[mt][nt][2] + bb0, d[mt][nt][3] + bb1);
            *(float2*)&g_xg[(size_t)r * G4 + col]       = v0;
            *(float2*)&g_xg[(size_t)(r + 8) * G4 + col] = v1;
        }
    }
}

// ---------------------------------------------------------------------------
// Persistent recurrent kernel. 64 blocks x 256 threads (8 warps).
// Block g owns h-cols [8g,8g+8) -> 32 gate cols j=q*8+ci (row n=q*512+hc0+ci).
// Per step: C[32 cols x 128 b] = Ws @ h^T via split-bf16 mma.
// Warp w owns b-rows 16w..16w+15 (m16 tile), 4 n8 tiles over the 32 cols.
// A(h) frags: LDG.64 from packed double-buffered g_hpk + byte_perm.
// B(W) frags: ldmatrix.x4 from smem (hi/lo split once at start).
// Cs stored transposed [col][b] (pitch 130) for conflict-free epilogue reads.
// ---------------------------------------------------------------------------
#define WPITCH 520
#define CPITCH 130
#define SM_WSH 0
#define SM_WSL (32 * WPITCH * 2)
#define SM_CS  (2 * 32 * WPITCH * 2)
#define SM_TOT (SM_CS + 32 * CPITCH * 4)

__global__ void __launch_bounds__(256, 1) lstm_rec(const float* __restrict__ Whh,
                                                   float* __restrict__ out,
                                                   int tail)
{
    extern __shared__ char smraw[];
    __nv_bfloat16* Wsh = (__nv_bfloat16*)(smraw + SM_WSH);
    __nv_bfloat16* Wsl = (__nv_bfloat16*)(smraw + SM_WSL);
    float*         Cs  = (float*)(smraw + SM_CS);

    const int tid  = threadIdx.x;
    const int lane = tid & 31;
    const int w    = tid >> 5;
    const int gid  = lane >> 2;
    const int tig  = lane & 3;
    const int hc0  = blockIdx.x * 8;

    // Load + split W_hh slice: Ws[j][k] = Whh[(j>>3)*512 + hc0 + (j&7)][k]
    for (int idx = tid; idx < 32 * 512; idx += 256) {
        int j = idx >> 9, k = idx & 511;
        int n = (j >> 3) * 512 + hc0 + (j & 7);
        float v = Whh[(size_t)n * HH + k];
        uint32_t hb, lb;
        split2(v, hb, lb);
        Wsh[j * WPITCH + k] = __ushort_as_bfloat16((unsigned short)hb);
        Wsl[j * WPITCH + k] = __ushort_as_bfloat16((unsigned short)lb);
    }
    __syncthreads();

    // ldmatrix.x4 lane mapping for B (covers an nt-pair: 16 rows x 16 k)
    const int b_mrow = ((lane >> 4) << 3) + (lane & 7);
    const int b_kofs = ((lane >> 3) & 1) << 3;
    const uint32_t uWsh = smem_u32(Wsh);
    const uint32_t uWsl = smem_u32(Wsl);

    const int arow = 16 * w + gid;            // A rows arow, arow+8
    const int ciq  = (tid >> 7) * 4;          // epilogue: 4 ci values
    const int eb   = tid & 127;               // epilogue: batch index
    float creg[4] = {0.f, 0.f, 0.f, 0.f};

    for (int t = 0; t < TT; ++t) {
        if (t > 0) {
            const uint32_t* hp = g_hpk[(t - 1) & 1];
            float d[4][4] = {{0.f}};

#pragma unroll 4
            for (int kk = 0; kk < 32; ++kk) {
                const int kb = kk * 16;
                uint2 v00 = *(const uint2*)(hp + (size_t)arow * 512 + kb + 2 * tig);
                uint2 v01 = *(const uint2*)(hp + (size_t)arow * 512 + kb + 8 + 2 * tig);
                uint2 v10 = *(const uint2*)(hp + (size_t)(arow + 8) * 512 + kb + 2 * tig);
                uint2 v11 = *(const uint2*)(hp + (size_t)(arow + 8) * 512 + kb + 8 + 2 * tig);
                uint32_t ah[4], al[4];
                ah[0] = __byte_perm(v00.x, v00.y, 0x5410);
                ah[1] = __byte_perm(v10.x, v10.y, 0x5410);
                ah[2] = __byte_perm(v01.x, v01.y, 0x5410);
                ah[3] = __byte_perm(v11.x, v11.y, 0x5410);
                al[0] = __byte_perm(v00.x, v00.y, 0x7632);
                al[1] = __byte_perm(v10.x, v10.y, 0x7632);
                al[2] = __byte_perm(v01.x, v01.y, 0x7632);
                al[3] = __byte_perm(v11.x, v11.y, 0x7632);

#pragma unroll
                for (int ntp = 0; ntp < 2; ++ntp) {   // nt pairs {0,1}, {2,3}
                    uint32_t off = (uint32_t)(((ntp * 16 + b_mrow) * WPITCH + kb + b_kofs) * 2);
                    uint32_t bh[4], bl[4];
                    ldmx4(bh[0], bh[1], bh[2], bh[3], uWsh + off);
                    ldmx4(bl[0], bl[1], bl[2], bl[3], uWsl + off);
                    mma_bf16(d[ntp * 2],     ah, bh);
                    mma_bf16(d[ntp * 2],     ah, bl);
                    mma_bf16(d[ntp * 2],     al, bh);
                    mma_bf16(d[ntp * 2 + 1], ah, bh + 2);
                    mma_bf16(d[ntp * 2 + 1], ah, bl + 2);
                    mma_bf16(d[ntp * 2 + 1], al, bh + 2);
                }
            }

            // dump C fragments transposed: Cs[col][b]
#pragma unroll
            for (int nt = 0; nt < 4; ++nt) {
                int c0 = nt * 8 + 2 * tig;
                Cs[c0 * CPITCH + arow]           = d[nt][0];
                Cs[(c0 + 1) * CPITCH + arow]     = d[nt][1];
                Cs[c0 * CPITCH + arow + 8]       = d[nt][2];
                Cs[(c0 + 1) * CPITCH + arow + 8] = d[nt][3];
            }
        }
        __syncthreads();

        // Fused fp32 LSTM elementwise: 1024 (b,ci) pairs, 4 per thread.
        const float* xgt = g_xg + (size_t)t * BB * G4;
        uint32_t* hw = g_hpk[t & 1];
        float4 xv[4];
#pragma unroll
        for (int q = 0; q < 4; ++q)
            xv[q] = *(const float4*)(xgt + (size_t)eb * G4 + q * 512 + hc0 + ciq);

        float hres[4];
#pragma unroll
        for (int i = 0; i < 4; ++i) {
            int ci = ciq + i;
            float g0 = ((const float*)&xv[0])[i];
            float g1 = ((const float*)&xv[1])[i];
            float g2 = ((const float*)&xv[2])[i];
            float g3 = ((const float*)&xv[3])[i];
            if (t > 0) {
                g0 += Cs[(0 * 8 + ci) * CPITCH + eb];
                g1 += Cs[(1 * 8 + ci) * CPITCH + eb];
                g2 += Cs[(2 * 8 + ci) * CPITCH + eb];
                g3 += Cs[(3 * 8 + ci) * CPITCH + eb];
            }
            float ig = 1.0f / (1.0f + __expf(-g0));
            float fg = 1.0f / (1.0f + __expf(-g1));
            float gg = tanhf(g2);
            float og = 1.0f / (1.0f + __expf(-g3));
            float cn = fg * creg[i] + ig * gg;
            creg[i] = cn;
            hres[i] = og * tanhf(cn);
        }
        // coalesced writes: fp32 out + packed bf16 hi/lo
        {
            int idx = eb * HH + hc0 + ciq;
            *(float4*)(out + (size_t)t * BB * HH + idx) =
                make_float4(hres[0], hres[1], hres[2], hres[3]);
            uint32_t pk[4];
#pragma unroll
            for (int i = 0; i < 4; ++i) {
                uint32_t hb, lb;
                split2(hres[i], hb, lb);
                pk[i] = hb | (lb << 16);
            }
            *(uint4*)(hw + idx) = make_uint4(pk[0], pk[1], pk[2], pk[3]);
        }

        // grid barrier between steps
        __syncthreads();
        if (tid == 0) {
            __threadfence();
            atomicAdd(&g_sync, 1u);
            unsigned target = (unsigned)(t + 1) * NBLK;
            while (*(volatile unsigned*)&g_sync < target) { }
            __threadfence();
        }
        __syncthreads();
    }

    // tail: hT copy + cT from registers
    if (tail) {
        int idx = eb * HH + hc0 + ciq;
        *(float4*)(out + TBH + idx) = *(const float4*)(out + (size_t)(TT - 1) * BB * HH + idx);
        *(float4*)(out + TBH + BB * HH + idx) = make_float4(creg[0], creg[1], creg[2], creg[3]);
    }
}

// ---------------------------------------------------------------------------
extern "C" void kernel_launch(void* const* d_in, const int* in_sizes, int n_in,
                              void* d_out, int out_size)
{
    const float* input = (const float*)d_in[0];
    /* d_in[1] = time, unused by the base cell */
    const float* W_ih  = (const float*)d_in[2];
    const float* W_hh  = (const float*)d_in[3];
    const float* b_ih  = (const float*)d_in[4];
    const float* b_hh  = (const float*)d_in[5];
    float* out = (float*)d_out;

    int tail = ((size_t)out_size >= TBH + 2ull * BB * HH) ? 1 : 0;

    convert_init<<<2048, 256>>>(input, W_ih, b_ih, b_hh);
    sgemm_bf16<<<dim3(16, 512), 256>>>();

    cudaFuncSetAttribute(lstm_rec, cudaFuncAttributeMaxDynamicSharedMemorySize, SM_TOT);
    lstm_rec<<<NBLK, 256, SM_TOT>>>(W_hh, out, tail);
}